// round 5
// baseline (speedup 1.0000x reference)
#include <cuda_runtime.h>
#include <cuda_bf16.h>
#include <stdint.h>

// Problem constants
#define T_TOK 2048
#define H_DIM 1024
#define I_DIM 768
#define E_NUM 8
#define K_TOP 2
#define A_TOT (T_TOK * K_TOP)   // 4096

// ---------------------------------------------------------------------------
// Device-global scratch (pre-split bf16 hi/lo copies + routing + outputs)
// ---------------------------------------------------------------------------
__device__ int   g_count[E_NUM];
__device__ int   g_offset[E_NUM];
__device__ int   g_perm[A_TOT];
__device__ int   g_slot[A_TOT];
__device__ __nv_bfloat16 g_xh[(size_t)T_TOK * H_DIM];
__device__ __nv_bfloat16 g_xl[(size_t)T_TOK * H_DIM];
__device__ __nv_bfloat16 g_wguh[(size_t)E_NUM * 2 * I_DIM * H_DIM];
__device__ __nv_bfloat16 g_wgul[(size_t)E_NUM * 2 * I_DIM * H_DIM];
__device__ __nv_bfloat16 g_wdh[(size_t)E_NUM * H_DIM * I_DIM];
__device__ __nv_bfloat16 g_wdl[(size_t)E_NUM * H_DIM * I_DIM];
__device__ __nv_bfloat16 g_acth[(size_t)A_TOT * I_DIM];
__device__ __nv_bfloat16 g_actl[(size_t)A_TOT * I_DIM];
__device__ float g_eo[(size_t)A_TOT * H_DIM];

// ---------------------------------------------------------------------------
// PTX helpers (base PTX, valid on sm_100 target)
// ---------------------------------------------------------------------------
__device__ __forceinline__ uint32_t smem_u32(const void* p) {
    uint32_t a;
    asm("{ .reg .u64 t; cvta.to.shared.u64 t, %1; cvt.u32.u64 %0, t; }" : "=r"(a) : "l"(p));
    return a;
}

#define LDSM_X4(R0, R1, R2, R3, ADDR) \
    asm volatile("ldmatrix.sync.aligned.m8n8.x4.shared.b16 {%0,%1,%2,%3}, [%4];" \
        : "=r"(R0), "=r"(R1), "=r"(R2), "=r"(R3) : "r"(ADDR))

#define MMA_BF16(D, A, B0, B1) \
    asm volatile("mma.sync.aligned.m16n8k16.row.col.f32.bf16.bf16.f32 " \
        "{%0,%1,%2,%3}, {%4,%5,%6,%7}, {%8,%9}, {%0,%1,%2,%3};" \
        : "+f"((D)[0]), "+f"((D)[1]), "+f"((D)[2]), "+f"((D)[3]) \
        : "r"((A)[0]), "r"((A)[1]), "r"((A)[2]), "r"((A)[3]), "r"(B0), "r"(B1))

#define CP_ASYNC16(DST, SRC, SZ) \
    asm volatile("cp.async.cg.shared.global [%0], [%1], 16, %2;" \
        :: "r"(DST), "l"(SRC), "r"(SZ))
#define CP_COMMIT  asm volatile("cp.async.commit_group;" ::: "memory")
#define CP_WAIT1   asm volatile("cp.async.wait_group 1;" ::: "memory")
#define CP_WAIT0   asm volatile("cp.async.wait_group 0;" ::: "memory")

// fp32x4 -> bf16 hi/lo packed pairs
__device__ __forceinline__ void split4(float4 v, uint2& uh, uint2& ul) {
    __nv_bfloat16 h0 = __float2bfloat16(v.x), h1 = __float2bfloat16(v.y);
    __nv_bfloat16 h2 = __float2bfloat16(v.z), h3 = __float2bfloat16(v.w);
    __nv_bfloat16 l0 = __float2bfloat16(v.x - __bfloat162float(h0));
    __nv_bfloat16 l1 = __float2bfloat16(v.y - __bfloat162float(h1));
    __nv_bfloat16 l2 = __float2bfloat16(v.z - __bfloat162float(h2));
    __nv_bfloat16 l3 = __float2bfloat16(v.w - __bfloat162float(h3));
    uh.x = (uint32_t)__bfloat16_as_ushort(h0) | ((uint32_t)__bfloat16_as_ushort(h1) << 16);
    uh.y = (uint32_t)__bfloat16_as_ushort(h2) | ((uint32_t)__bfloat16_as_ushort(h3) << 16);
    ul.x = (uint32_t)__bfloat16_as_ushort(l0) | ((uint32_t)__bfloat16_as_ushort(l1) << 16);
    ul.y = (uint32_t)__bfloat16_as_ushort(l2) | ((uint32_t)__bfloat16_as_ushort(l3) << 16);
}

// ---------------------------------------------------------------------------
// Conversion kernels: fp32 -> (hi, lo) bf16
// ---------------------------------------------------------------------------
__device__ __forceinline__ void conv_body(const float* __restrict__ src,
                                          __nv_bfloat16* __restrict__ hi,
                                          __nv_bfloat16* __restrict__ lo, int n4) {
    int i = blockIdx.x * blockDim.x + threadIdx.x;
    int stride = gridDim.x * blockDim.x;
    for (; i < n4; i += stride) {
        float4 v = ((const float4*)src)[i];
        uint2 uh, ul;
        split4(v, uh, ul);
        ((uint2*)hi)[i] = uh;
        ((uint2*)lo)[i] = ul;
    }
}
__global__ void conv_x(const float* __restrict__ s)   { conv_body(s, g_xh,   g_xl,   T_TOK * H_DIM / 4); }
__global__ void conv_wgu(const float* __restrict__ s) { conv_body(s, g_wguh, g_wgul, E_NUM * 2 * I_DIM * H_DIM / 4); }
__global__ void conv_wd(const float* __restrict__ s)  { conv_body(s, g_wdh,  g_wdl,  E_NUM * H_DIM * I_DIM / 4); }

// ---------------------------------------------------------------------------
// Routing: single block
// ---------------------------------------------------------------------------
__global__ void route_all(const int* __restrict__ topk) {
    __shared__ int cnt[E_NUM], cur[E_NUM];
    int tid = threadIdx.x;
    if (tid < E_NUM) cnt[tid] = 0;
    __syncthreads();
    for (int a = tid; a < A_TOT; a += blockDim.x) atomicAdd(&cnt[topk[a]], 1);
    __syncthreads();
    if (tid == 0) {
        int s = 0;
        for (int e = 0; e < E_NUM; e++) {
            g_count[e] = cnt[e];
            g_offset[e] = s;
            cur[e] = s;
            s += cnt[e];
        }
    }
    __syncthreads();
    for (int a = tid; a < A_TOT; a += blockDim.x) {
        int e = topk[a];
        int s = atomicAdd(&cur[e], 1);
        g_perm[s] = a;
        g_slot[a] = s;
    }
}

// ---------------------------------------------------------------------------
// SMEM layout: KC=32 bf16 cols padded to stride 40.
// Stage: Ah(128x40) | Al(128x40) | Bh(256x40) | Bl(256x40)
// ---------------------------------------------------------------------------
#define KC       32
#define STRIDE   40
#define A_TILE_E (128 * STRIDE)   // 5120
#define B_TILE_E (256 * STRIDE)   // 10240
#define STAGE_E  (2 * A_TILE_E + 2 * B_TILE_E)  // 30720
#define SMEM_BYTES (2 * STAGE_E * 2)            // 122880

__device__ __forceinline__ void load_afrag(uint32_t sb, int eoff, int row0, int kk,
                                           int lane, uint32_t a[4]) {
    int row = row0 + (lane & 15);
    int col = kk + ((lane >> 4) << 3);
    uint32_t addr = sb + (uint32_t)(eoff + row * STRIDE + col) * 2;
    LDSM_X4(a[0], a[1], a[2], a[3], addr);
}
__device__ __forceinline__ void load_bfrag(uint32_t sb, int eoff, int nbase, int kk,
                                           int lane, uint32_t b[4]) {
    int row = nbase + (((lane >> 4) & 1) << 3) + (lane & 7);
    int col = kk + (((lane >> 3) & 1) << 3);
    uint32_t addr = sb + (uint32_t)(eoff + row * STRIDE + col) * 2;
    LDSM_X4(b[0], b[1], b[2], b[3], addr);
}

// ---------------------------------------------------------------------------
// GEMM1: act = silu(X*Wg^T) * (X*Wu^T).
// Block: 128 slots x (128 gate + 128 up). 512 threads, 16 warps (4M x 4N).
// ---------------------------------------------------------------------------
#define NCH1 (H_DIM / KC)   // 32

__global__ __launch_bounds__(512, 1)
void gemm1(void) {
    const int e   = blockIdx.z;
    const int cnt = g_count[e];
    const int m0  = blockIdx.x * 128;
    if (m0 >= cnt) return;
    const int off  = g_offset[e];
    const int n0g  = blockIdx.y * 128;
    const int cntm = cnt - m0;

    extern __shared__ __nv_bfloat16 smem[];
    __shared__ int rowtok[128];
    const uint32_t sb = smem_u32(smem);

    const int tid = threadIdx.x, lane = tid & 31, wid = tid >> 5;
    const int wm = wid & 3, wn = wid >> 2;   // 4 x 4

    if (tid < 128)
        rowtok[tid] = (tid < cntm) ? g_perm[off + m0 + tid] / K_TOP : -1;
    __syncthreads();

    const __nv_bfloat16* wh = g_wguh + (size_t)e * (2 * I_DIM) * H_DIM;
    const __nv_bfloat16* wl = g_wgul + (size_t)e * (2 * I_DIM) * H_DIM;

    // issue one stage: 1024 A cp16 + 2048 B cp16, 6 per thread
    auto issue = [&](int k0, int soE) {
        #pragma unroll
        for (int i = 0; i < 6; i++) {
            int idx = tid + i * 512;
            if (idx < 1024) {               // A tiles (hi, lo)
                int mat = idx >> 9;         // 0=Ah 1=Al
                int row = (idx >> 2) & 127;
                int seg = idx & 3;
                uint32_t dst = sb + (uint32_t)(soE + mat * A_TILE_E + row * STRIDE + seg * 8) * 2;
                int tok = rowtok[row];
                const __nv_bfloat16* base = mat ? g_xl : g_xh;
                const __nv_bfloat16* src = base + (size_t)(tok < 0 ? 0 : tok) * H_DIM + k0 + seg * 8;
                CP_ASYNC16(dst, src, (tok < 0) ? 0u : 16u);
            } else {                        // B tiles (hi, lo), 256 rows
                int j   = idx - 1024;
                int mat = j >> 10;          // 0=Bh 1=Bl
                int row = (j >> 2) & 255;
                int seg = j & 3;
                uint32_t dst = sb + (uint32_t)(soE + 2 * A_TILE_E + mat * B_TILE_E + row * STRIDE + seg * 8) * 2;
                int wr = (row < 128) ? (n0g + row) : (I_DIM + n0g + row - 128);
                const __nv_bfloat16* base = mat ? wl : wh;
                const __nv_bfloat16* src = base + (size_t)wr * H_DIM + k0 + seg * 8;
                CP_ASYNC16(dst, src, 16u);
            }
        }
        CP_COMMIT;
    };

    float accG[2][4][4], accU[2][4][4];
    #pragma unroll
    for (int a = 0; a < 2; a++)
        #pragma unroll
        for (int b = 0; b < 4; b++)
            #pragma unroll
            for (int c = 0; c < 4; c++) { accG[a][b][c] = 0.f; accU[a][b][c] = 0.f; }

    issue(0, 0);

    for (int c = 0; c < NCH1; c++) {
        const int s = c & 1;
        if (c + 1 < NCH1) { issue((c + 1) * KC, (s ^ 1) * STAGE_E); CP_WAIT1; }
        else CP_WAIT0;
        __syncthreads();

        const int so = s * STAGE_E;
        const int bo = so + 2 * A_TILE_E;
        #pragma unroll
        for (int kk = 0; kk < KC; kk += 16) {
            uint32_t ah[2][4], al[2][4];
            #pragma unroll
            for (int mt = 0; mt < 2; mt++) {
                load_afrag(sb, so + 0 * A_TILE_E, wm * 32 + mt * 16, kk, lane, ah[mt]);
                load_afrag(sb, so + 1 * A_TILE_E, wm * 32 + mt * 16, kk, lane, al[mt]);
            }
            #pragma unroll
            for (int p = 0; p < 2; p++) {
                const int nbg = wn * 32 + p * 16;
                uint32_t bgh[4], bgl[4], buh[4], bul[4];
                load_bfrag(sb, bo + 0 * B_TILE_E, nbg,       kk, lane, bgh);
                load_bfrag(sb, bo + 1 * B_TILE_E, nbg,       kk, lane, bgl);
                load_bfrag(sb, bo + 0 * B_TILE_E, nbg + 128, kk, lane, buh);
                load_bfrag(sb, bo + 1 * B_TILE_E, nbg + 128, kk, lane, bul);
                #pragma unroll
                for (int mt = 0; mt < 2; mt++) {
                    #pragma unroll
                    for (int q = 0; q < 2; q++) {
                        float* dG = accG[mt][2 * p + q];
                        float* dU = accU[mt][2 * p + q];
                        MMA_BF16(dG, ah[mt], bgh[2 * q], bgh[2 * q + 1]);
                        MMA_BF16(dG, ah[mt], bgl[2 * q], bgl[2 * q + 1]);
                        MMA_BF16(dG, al[mt], bgh[2 * q], bgh[2 * q + 1]);
                        MMA_BF16(dU, ah[mt], buh[2 * q], buh[2 * q + 1]);
                        MMA_BF16(dU, ah[mt], bul[2 * q], bul[2 * q + 1]);
                        MMA_BF16(dU, al[mt], buh[2 * q], buh[2 * q + 1]);
                    }
                }
            }
        }
        __syncthreads();
    }

    // epilogue: silu(gate)*up -> bf16 hi/lo act arrays
    const int gid = lane >> 2, tig = lane & 3;
    #pragma unroll
    for (int mt = 0; mt < 2; mt++) {
        #pragma unroll
        for (int nt = 0; nt < 4; nt++) {
            int colg = n0g + wn * 32 + nt * 8 + 2 * tig;
            #pragma unroll
            for (int h = 0; h < 2; h++) {
                int rowl = wm * 32 + mt * 16 + gid + h * 8;
                if (rowl < cntm) {
                    float g0 = accG[mt][nt][2 * h],     u0 = accU[mt][nt][2 * h];
                    float g1 = accG[mt][nt][2 * h + 1], u1 = accU[mt][nt][2 * h + 1];
                    float v0 = (g0 / (1.f + __expf(-g0))) * u0;
                    float v1 = (g1 / (1.f + __expf(-g1))) * u1;
                    __nv_bfloat16 h0 = __float2bfloat16(v0);
                    __nv_bfloat16 h1 = __float2bfloat16(v1);
                    __nv_bfloat16 l0 = __float2bfloat16(v0 - __bfloat162float(h0));
                    __nv_bfloat16 l1 = __float2bfloat16(v1 - __bfloat162float(h1));
                    size_t o = (size_t)(off + m0 + rowl) * I_DIM + colg;
                    *(uint32_t*)(g_acth + o) =
                        (uint32_t)__bfloat16_as_ushort(h0) | ((uint32_t)__bfloat16_as_ushort(h1) << 16);
                    *(uint32_t*)(g_actl + o) =
                        (uint32_t)__bfloat16_as_ushort(l0) | ((uint32_t)__bfloat16_as_ushort(l1) << 16);
                }
            }
        }
    }
}

// ---------------------------------------------------------------------------
// GEMM2: eo = act * Wd^T.  Block: 128 slots x 256 H cols. 512 threads.
// ---------------------------------------------------------------------------
#define NCH2 (I_DIM / KC)   // 24

__global__ __launch_bounds__(512, 1)
void gemm2(void) {
    const int e   = blockIdx.z;
    const int cnt = g_count[e];
    const int m0  = blockIdx.x * 128;
    if (m0 >= cnt) return;
    const int off  = g_offset[e];
    const int n0   = blockIdx.y * 256;
    const int cntm = cnt - m0;

    extern __shared__ __nv_bfloat16 smem[];
    const uint32_t sb = smem_u32(smem);

    const int tid = threadIdx.x, lane = tid & 31, wid = tid >> 5;
    const int wm = wid & 3, wn = wid >> 2;

    const __nv_bfloat16* wh = g_wdh + (size_t)e * H_DIM * I_DIM;
    const __nv_bfloat16* wl = g_wdl + (size_t)e * H_DIM * I_DIM;

    auto issue = [&](int k0, int soE) {
        #pragma unroll
        for (int i = 0; i < 6; i++) {
            int idx = tid + i * 512;
            if (idx < 1024) {
                int mat = idx >> 9;
                int row = (idx >> 2) & 127;
                int seg = idx & 3;
                uint32_t dst = sb + (uint32_t)(soE + mat * A_TILE_E + row * STRIDE + seg * 8) * 2;
                const __nv_bfloat16* base = mat ? g_actl : g_acth;
                int r = (row < cntm) ? row : 0;
                const __nv_bfloat16* src = base + (size_t)(off + m0 + r) * I_DIM + k0 + seg * 8;
                CP_ASYNC16(dst, src, (row < cntm) ? 16u : 0u);
            } else {
                int j   = idx - 1024;
                int mat = j >> 10;
                int row = (j >> 2) & 255;
                int seg = j & 3;
                uint32_t dst = sb + (uint32_t)(soE + 2 * A_TILE_E + mat * B_TILE_E + row * STRIDE + seg * 8) * 2;
                const __nv_bfloat16* base = mat ? wl : wh;
                const __nv_bfloat16* src = base + (size_t)(n0 + row) * I_DIM + k0 + seg * 8;
                CP_ASYNC16(dst, src, 16u);
            }
        }
        CP_COMMIT;
    };

    float acc[2][8][4];
    #pragma unroll
    for (int a = 0; a < 2; a++)
        #pragma unroll
        for (int b = 0; b < 8; b++)
            #pragma unroll
            for (int c = 0; c < 4; c++) acc[a][b][c] = 0.f;

    issue(0, 0);

    for (int c = 0; c < NCH2; c++) {
        const int s = c & 1;
        if (c + 1 < NCH2) { issue((c + 1) * KC, (s ^ 1) * STAGE_E); CP_WAIT1; }
        else CP_WAIT0;
        __syncthreads();

        const int so = s * STAGE_E;
        const int bo = so + 2 * A_TILE_E;
        #pragma unroll
        for (int kk = 0; kk < KC; kk += 16) {
            uint32_t ah[2][4], al[2][4];
            #pragma unroll
            for (int mt = 0; mt < 2; mt++) {
                load_afrag(sb, so + 0 * A_TILE_E, wm * 32 + mt * 16, kk, lane, ah[mt]);
                load_afrag(sb, so + 1 * A_TILE_E, wm * 32 + mt * 16, kk, lane, al[mt]);
            }
            #pragma unroll
            for (int p = 0; p < 4; p++) {
                const int nb = wn * 64 + p * 16;
                uint32_t bh[4], bl[4];
                load_bfrag(sb, bo + 0 * B_TILE_E, nb, kk, lane, bh);
                load_bfrag(sb, bo + 1 * B_TILE_E, nb, kk, lane, bl);
                #pragma unroll
                for (int mt = 0; mt < 2; mt++) {
                    #pragma unroll
                    for (int q = 0; q < 2; q++) {
                        float* d = acc[mt][2 * p + q];
                        MMA_BF16(d, ah[mt], bh[2 * q], bh[2 * q + 1]);
                        MMA_BF16(d, ah[mt], bl[2 * q], bl[2 * q + 1]);
                        MMA_BF16(d, al[mt], bh[2 * q], bh[2 * q + 1]);
                    }
                }
            }
        }
        __syncthreads();
    }

    const int gid = lane >> 2, tig = lane & 3;
    #pragma unroll
    for (int mt = 0; mt < 2; mt++) {
        #pragma unroll
        for (int nt = 0; nt < 8; nt++) {
            int col = n0 + wn * 64 + nt * 8 + 2 * tig;
            #pragma unroll
            for (int h = 0; h < 2; h++) {
                int rowl = wm * 32 + mt * 16 + gid + h * 8;
                if (rowl < cntm) {
                    float2 r = make_float2(acc[mt][nt][2 * h], acc[mt][nt][2 * h + 1]);
                    *(float2*)(g_eo + (size_t)(off + m0 + rowl) * H_DIM + col) = r;
                }
            }
        }
    }
}

// ---------------------------------------------------------------------------
// Combine
// ---------------------------------------------------------------------------
__global__ void combine(const float* __restrict__ wts, float* __restrict__ out) {
    int idx = blockIdx.x * blockDim.x + threadIdx.x;
    if (idx >= T_TOK * H_DIM / 4) return;
    int t  = idx / (H_DIM / 4);
    int h4 = idx % (H_DIM / 4);
    float w0 = wts[t * K_TOP + 0];
    float w1 = wts[t * K_TOP + 1];
    int s0 = g_slot[t * K_TOP + 0];
    int s1 = g_slot[t * K_TOP + 1];
    float4 a = ((const float4*)(g_eo + (size_t)s0 * H_DIM))[h4];
    float4 b = ((const float4*)(g_eo + (size_t)s1 * H_DIM))[h4];
    float4 r;
    r.x = w0 * a.x + w1 * b.x;
    r.y = w0 * a.y + w1 * b.y;
    r.z = w0 * a.z + w1 * b.z;
    r.w = w0 * a.w + w1 * b.w;
    ((float4*)out)[idx] = r;
}

// ---------------------------------------------------------------------------
// Launch
// ---------------------------------------------------------------------------
extern "C" void kernel_launch(void* const* d_in, const int* in_sizes, int n_in,
                              void* d_out, int out_size) {
    const float* X    = (const float*)d_in[0];
    const float* Wgu  = (const float*)d_in[1];
    const float* Wd   = (const float*)d_in[2];
    const int*   topk = (const int*)  d_in[3];
    const float* wts  = (const float*)d_in[4];
    float*       out  = (float*)d_out;

    cudaFuncSetAttribute(gemm1, cudaFuncAttributeMaxDynamicSharedMemorySize, SMEM_BYTES);
    cudaFuncSetAttribute(gemm2, cudaFuncAttributeMaxDynamicSharedMemorySize, SMEM_BYTES);

    route_all<<<1, 1024>>>(topk);
    conv_x  <<<512, 256>>>(X);
    conv_wgu<<<2048, 256>>>(Wgu);
    conv_wd <<<1024, 256>>>(Wd);

    dim3 g1(A_TOT / 128, I_DIM / 128, E_NUM);   // (32, 6, 8)
    gemm1<<<g1, 512, SMEM_BYTES>>>();

    dim3 g2(A_TOT / 128, H_DIM / 256, E_NUM);   // (32, 4, 8)
    gemm2<<<g2, 512, SMEM_BYTES>>>();

    combine<<<(T_TOK * H_DIM / 4 + 255) / 256, 256>>>(wts, out);
}

// round 6
// speedup vs baseline: 1.4835x; 1.4835x over previous
#include <cuda_runtime.h>
#include <cuda_fp16.h>
#include <stdint.h>

// Problem constants
#define T_TOK 2048
#define H_DIM 1024
#define I_DIM 768
#define E_NUM 8
#define K_TOP 2
#define A_TOT (T_TOK * K_TOP)   // 4096

// ---------------------------------------------------------------------------
// Device-global scratch
// ---------------------------------------------------------------------------
__device__ int   g_count[E_NUM];
__device__ int   g_offset[E_NUM];
__device__ int   g_perm[A_TOT];
__device__ int   g_slot[A_TOT];
__device__ __half g_xh[(size_t)T_TOK * H_DIM];
__device__ __half g_xl[(size_t)T_TOK * H_DIM];
__device__ __half g_wgu[(size_t)E_NUM * 2 * I_DIM * H_DIM];   // fp16, hi only
__device__ __half g_wd [(size_t)E_NUM * H_DIM * I_DIM];       // fp16, hi only
__device__ __half g_acth[(size_t)A_TOT * I_DIM];
__device__ __half g_actl[(size_t)A_TOT * I_DIM];
__device__ float g_eo[(size_t)A_TOT * H_DIM];

// ---------------------------------------------------------------------------
// PTX helpers (base PTX, valid on sm_100 target)
// ---------------------------------------------------------------------------
__device__ __forceinline__ uint32_t smem_u32(const void* p) {
    uint32_t a;
    asm("{ .reg .u64 t; cvta.to.shared.u64 t, %1; cvt.u32.u64 %0, t; }" : "=r"(a) : "l"(p));
    return a;
}

#define LDSM_X4(R0, R1, R2, R3, ADDR) \
    asm volatile("ldmatrix.sync.aligned.m8n8.x4.shared.b16 {%0,%1,%2,%3}, [%4];" \
        : "=r"(R0), "=r"(R1), "=r"(R2), "=r"(R3) : "r"(ADDR))

#define MMA_F16(D, A, B0, B1) \
    asm volatile("mma.sync.aligned.m16n8k16.row.col.f32.f16.f16.f32 " \
        "{%0,%1,%2,%3}, {%4,%5,%6,%7}, {%8,%9}, {%0,%1,%2,%3};" \
        : "+f"((D)[0]), "+f"((D)[1]), "+f"((D)[2]), "+f"((D)[3]) \
        : "r"((A)[0]), "r"((A)[1]), "r"((A)[2]), "r"((A)[3]), "r"(B0), "r"(B1))

#define CP_ASYNC16(DST, SRC, SZ) \
    asm volatile("cp.async.cg.shared.global [%0], [%1], 16, %2;" \
        :: "r"(DST), "l"(SRC), "r"(SZ))
#define CP_COMMIT  asm volatile("cp.async.commit_group;" ::: "memory")
#define CP_WAIT1   asm volatile("cp.async.wait_group 1;" ::: "memory")
#define CP_WAIT0   asm volatile("cp.async.wait_group 0;" ::: "memory")

__device__ __forceinline__ uint32_t pack_h2(__half a, __half b) {
    return (uint32_t)__half_as_ushort(a) | ((uint32_t)__half_as_ushort(b) << 16);
}

// fp32x4 -> fp16 hi/lo packed pairs
__device__ __forceinline__ void split4h(float4 v, uint2& uh, uint2& ul) {
    __half h0 = __float2half_rn(v.x), h1 = __float2half_rn(v.y);
    __half h2 = __float2half_rn(v.z), h3 = __float2half_rn(v.w);
    __half l0 = __float2half_rn(v.x - __half2float(h0));
    __half l1 = __float2half_rn(v.y - __half2float(h1));
    __half l2 = __float2half_rn(v.z - __half2float(h2));
    __half l3 = __float2half_rn(v.w - __half2float(h3));
    uh.x = pack_h2(h0, h1); uh.y = pack_h2(h2, h3);
    ul.x = pack_h2(l0, l1); ul.y = pack_h2(l2, l3);
}

// ---------------------------------------------------------------------------
// Conversion kernels
// ---------------------------------------------------------------------------
__global__ void conv_x(const float* __restrict__ src) {
    int i = blockIdx.x * blockDim.x + threadIdx.x;
    int stride = gridDim.x * blockDim.x;
    int n4 = T_TOK * H_DIM / 4;
    for (; i < n4; i += stride) {
        float4 v = ((const float4*)src)[i];
        uint2 uh, ul;
        split4h(v, uh, ul);
        ((uint2*)g_xh)[i] = uh;
        ((uint2*)g_xl)[i] = ul;
    }
}

__device__ __forceinline__ void conv_half_body(const float* __restrict__ src,
                                               __half* __restrict__ dst, int n4) {
    int i = blockIdx.x * blockDim.x + threadIdx.x;
    int stride = gridDim.x * blockDim.x;
    for (; i < n4; i += stride) {
        float4 v = ((const float4*)src)[i];
        uint2 u;
        u.x = pack_h2(__float2half_rn(v.x), __float2half_rn(v.y));
        u.y = pack_h2(__float2half_rn(v.z), __float2half_rn(v.w));
        ((uint2*)dst)[i] = u;
    }
}
__global__ void conv_wgu(const float* __restrict__ s) { conv_half_body(s, g_wgu, E_NUM * 2 * I_DIM * H_DIM / 4); }
__global__ void conv_wd (const float* __restrict__ s) { conv_half_body(s, g_wd,  E_NUM * H_DIM * I_DIM / 4); }

// ---------------------------------------------------------------------------
// Routing: single block
// ---------------------------------------------------------------------------
__global__ void route_all(const int* __restrict__ topk) {
    __shared__ int cnt[E_NUM], cur[E_NUM];
    int tid = threadIdx.x;
    if (tid < E_NUM) cnt[tid] = 0;
    __syncthreads();
    for (int a = tid; a < A_TOT; a += blockDim.x) atomicAdd(&cnt[topk[a]], 1);
    __syncthreads();
    if (tid == 0) {
        int s = 0;
        for (int e = 0; e < E_NUM; e++) {
            g_count[e] = cnt[e];
            g_offset[e] = s;
            cur[e] = s;
            s += cnt[e];
        }
    }
    __syncthreads();
    for (int a = tid; a < A_TOT; a += blockDim.x) {
        int e = topk[a];
        int s = atomicAdd(&cur[e], 1);
        g_perm[s] = a;
        g_slot[a] = s;
    }
}

// ---------------------------------------------------------------------------
// SMEM layout: KC=32 fp16 cols padded to stride 40.
// Per stage: Ah(128x40) | Al(128x40) | B(128x40)
// ---------------------------------------------------------------------------
#define KC       32
#define STRIDE   40
#define TILE_E   (128 * STRIDE)       // 5120 elems
#define STAGE_E  (3 * TILE_E)         // 15360
#define SMEM_BYTES (2 * STAGE_E * 2)  // 61440 B

__device__ __forceinline__ void load_afrag(uint32_t sb, int eoff, int row0, int kk,
                                           int lane, uint32_t a[4]) {
    int row = row0 + (lane & 15);
    int col = kk + ((lane >> 4) << 3);
    uint32_t addr = sb + (uint32_t)(eoff + row * STRIDE + col) * 2;
    LDSM_X4(a[0], a[1], a[2], a[3], addr);
}
__device__ __forceinline__ void load_bfrag(uint32_t sb, int eoff, int nbase, int kk,
                                           int lane, uint32_t b[4]) {
    int row = nbase + (((lane >> 4) & 1) << 3) + (lane & 7);
    int col = kk + (((lane >> 3) & 1) << 3);
    uint32_t addr = sb + (uint32_t)(eoff + row * STRIDE + col) * 2;
    LDSM_X4(b[0], b[1], b[2], b[3], addr);
}

// ---------------------------------------------------------------------------
// GEMM1: act = silu(X*Wg^T) * (X*Wu^T).  Block 128 slots x (64 gate + 64 up).
// 256 threads, 8 warps (4M x 2N), 2 CTAs/SM.
// D = Ah*B + Al*B  (A fp16-split, B single fp16)
// ---------------------------------------------------------------------------
#define NCH1 (H_DIM / KC)   // 32

__global__ __launch_bounds__(256, 2)
void gemm1(void) {
    const int e   = blockIdx.z;
    const int cnt = g_count[e];
    const int m0  = blockIdx.x * 128;
    if (m0 >= cnt) return;
    const int off  = g_offset[e];
    const int n0g  = blockIdx.y * 64;
    const int cntm = cnt - m0;

    extern __shared__ __half smem[];
    __shared__ int rowtok[128];
    const uint32_t sb = smem_u32(smem);

    const int tid = threadIdx.x, lane = tid & 31, wid = tid >> 5;
    const int wm = wid & 3, wn = wid >> 2;

    if (tid < 128)
        rowtok[tid] = (tid < cntm) ? g_perm[off + m0 + tid] / K_TOP : -1;
    __syncthreads();

    const __half* wb = g_wgu + (size_t)e * (2 * I_DIM) * H_DIM;

    // issue one stage: 1536 cp16, 6 per thread
    auto issue = [&](int k0, int soE) {
        #pragma unroll
        for (int i = 0; i < 6; i++) {
            int idx = tid + i * 256;
            int mat = idx >> 9;              // 0=Ah 1=Al 2=B
            int row = (idx >> 2) & 127;
            int seg = idx & 3;
            uint32_t dst = sb + (uint32_t)(soE + mat * TILE_E + row * STRIDE + seg * 8) * 2;
            if (mat < 2) {
                int tok = rowtok[row];
                const __half* base = mat ? g_xl : g_xh;
                const __half* src = base + (size_t)(tok < 0 ? 0 : tok) * H_DIM + k0 + seg * 8;
                CP_ASYNC16(dst, src, (tok < 0) ? 0u : 16u);
            } else {
                int wr = (row < 64) ? (n0g + row) : (I_DIM + n0g + row - 64);
                const __half* src = wb + (size_t)wr * H_DIM + k0 + seg * 8;
                CP_ASYNC16(dst, src, 16u);
            }
        }
        CP_COMMIT;
    };

    float accG[2][4][4], accU[2][4][4];
    #pragma unroll
    for (int a = 0; a < 2; a++)
        #pragma unroll
        for (int b = 0; b < 4; b++)
            #pragma unroll
            for (int c = 0; c < 4; c++) { accG[a][b][c] = 0.f; accU[a][b][c] = 0.f; }

    issue(0, 0);

    for (int c = 0; c < NCH1; c++) {
        const int s = c & 1;
        if (c + 1 < NCH1) { issue((c + 1) * KC, (s ^ 1) * STAGE_E); CP_WAIT1; }
        else CP_WAIT0;
        __syncthreads();

        const int so = s * STAGE_E;
        #pragma unroll
        for (int kk = 0; kk < KC; kk += 16) {
            uint32_t ah[2][4], al[2][4];
            #pragma unroll
            for (int mt = 0; mt < 2; mt++) {
                load_afrag(sb, so + 0 * TILE_E, wm * 32 + mt * 16, kk, lane, ah[mt]);
                load_afrag(sb, so + 1 * TILE_E, wm * 32 + mt * 16, kk, lane, al[mt]);
            }
            #pragma unroll
            for (int p = 0; p < 2; p++) {
                const int nbg = wn * 32 + p * 16;
                uint32_t bg[4], bu[4];
                load_bfrag(sb, so + 2 * TILE_E, nbg,      kk, lane, bg);
                load_bfrag(sb, so + 2 * TILE_E, nbg + 64, kk, lane, bu);
                #pragma unroll
                for (int mt = 0; mt < 2; mt++) {
                    #pragma unroll
                    for (int q = 0; q < 2; q++) {
                        float* dG = accG[mt][2 * p + q];
                        float* dU = accU[mt][2 * p + q];
                        MMA_F16(dG, ah[mt], bg[2 * q], bg[2 * q + 1]);
                        MMA_F16(dG, al[mt], bg[2 * q], bg[2 * q + 1]);
                        MMA_F16(dU, ah[mt], bu[2 * q], bu[2 * q + 1]);
                        MMA_F16(dU, al[mt], bu[2 * q], bu[2 * q + 1]);
                    }
                }
            }
        }
        __syncthreads();
    }

    // epilogue: silu(gate)*up -> fp16 hi/lo act arrays
    const int gid = lane >> 2, tig = lane & 3;
    #pragma unroll
    for (int mt = 0; mt < 2; mt++) {
        #pragma unroll
        for (int nt = 0; nt < 4; nt++) {
            int colg = n0g + wn * 32 + nt * 8 + 2 * tig;
            #pragma unroll
            for (int h = 0; h < 2; h++) {
                int rowl = wm * 32 + mt * 16 + gid + h * 8;
                if (rowl < cntm) {
                    float g0 = accG[mt][nt][2 * h],     u0 = accU[mt][nt][2 * h];
                    float g1 = accG[mt][nt][2 * h + 1], u1 = accU[mt][nt][2 * h + 1];
                    float v0 = (g0 / (1.f + __expf(-g0))) * u0;
                    float v1 = (g1 / (1.f + __expf(-g1))) * u1;
                    __half h0 = __float2half_rn(v0);
                    __half h1 = __float2half_rn(v1);
                    __half l0 = __float2half_rn(v0 - __half2float(h0));
                    __half l1 = __float2half_rn(v1 - __half2float(h1));
                    size_t o = (size_t)(off + m0 + rowl) * I_DIM + colg;
                    *(uint32_t*)(g_acth + o) = pack_h2(h0, h1);
                    *(uint32_t*)(g_actl + o) = pack_h2(l0, l1);
                }
            }
        }
    }
}

// ---------------------------------------------------------------------------
// GEMM2: eo = act * Wd^T.  Block 128 slots x 128 H cols, K = 768.
// ---------------------------------------------------------------------------
#define NCH2 (I_DIM / KC)   // 24

__global__ __launch_bounds__(256, 2)
void gemm2(void) {
    const int e   = blockIdx.z;
    const int cnt = g_count[e];
    const int m0  = blockIdx.x * 128;
    if (m0 >= cnt) return;
    const int off  = g_offset[e];
    const int n0   = blockIdx.y * 128;
    const int cntm = cnt - m0;

    extern __shared__ __half smem[];
    const uint32_t sb = smem_u32(smem);

    const int tid = threadIdx.x, lane = tid & 31, wid = tid >> 5;
    const int wm = wid & 3, wn = wid >> 2;

    const __half* wb = g_wd + (size_t)e * H_DIM * I_DIM;

    auto issue = [&](int k0, int soE) {
        #pragma unroll
        for (int i = 0; i < 6; i++) {
            int idx = tid + i * 256;
            int mat = idx >> 9;
            int row = (idx >> 2) & 127;
            int seg = idx & 3;
            uint32_t dst = sb + (uint32_t)(soE + mat * TILE_E + row * STRIDE + seg * 8) * 2;
            if (mat < 2) {
                const __half* base = mat ? g_actl : g_acth;
                int r = (row < cntm) ? row : 0;
                const __half* src = base + (size_t)(off + m0 + r) * I_DIM + k0 + seg * 8;
                CP_ASYNC16(dst, src, (row < cntm) ? 16u : 0u);
            } else {
                const __half* src = wb + (size_t)(n0 + row) * I_DIM + k0 + seg * 8;
                CP_ASYNC16(dst, src, 16u);
            }
        }
        CP_COMMIT;
    };

    float acc[2][8][4];
    #pragma unroll
    for (int a = 0; a < 2; a++)
        #pragma unroll
        for (int b = 0; b < 8; b++)
            #pragma unroll
            for (int c = 0; c < 4; c++) acc[a][b][c] = 0.f;

    issue(0, 0);

    for (int c = 0; c < NCH2; c++) {
        const int s = c & 1;
        if (c + 1 < NCH2) { issue((c + 1) * KC, (s ^ 1) * STAGE_E); CP_WAIT1; }
        else CP_WAIT0;
        __syncthreads();

        const int so = s * STAGE_E;
        #pragma unroll
        for (int kk = 0; kk < KC; kk += 16) {
            uint32_t ah[2][4], al[2][4];
            #pragma unroll
            for (int mt = 0; mt < 2; mt++) {
                load_afrag(sb, so + 0 * TILE_E, wm * 32 + mt * 16, kk, lane, ah[mt]);
                load_afrag(sb, so + 1 * TILE_E, wm * 32 + mt * 16, kk, lane, al[mt]);
            }
            #pragma unroll
            for (int p = 0; p < 4; p++) {
                const int nb = wn * 64 + p * 16;
                uint32_t bh[4];
                load_bfrag(sb, so + 2 * TILE_E, nb, kk, lane, bh);
                #pragma unroll
                for (int mt = 0; mt < 2; mt++) {
                    #pragma unroll
                    for (int q = 0; q < 2; q++) {
                        float* d = acc[mt][2 * p + q];
                        MMA_F16(d, ah[mt], bh[2 * q], bh[2 * q + 1]);
                        MMA_F16(d, al[mt], bh[2 * q], bh[2 * q + 1]);
                    }
                }
            }
        }
        __syncthreads();
    }

    const int gid = lane >> 2, tig = lane & 3;
    #pragma unroll
    for (int mt = 0; mt < 2; mt++) {
        #pragma unroll
        for (int nt = 0; nt < 8; nt++) {
            int col = n0 + wn * 64 + nt * 8 + 2 * tig;
            #pragma unroll
            for (int h = 0; h < 2; h++) {
                int rowl = wm * 32 + mt * 16 + gid + h * 8;
                if (rowl < cntm) {
                    float2 r = make_float2(acc[mt][nt][2 * h], acc[mt][nt][2 * h + 1]);
                    *(float2*)(g_eo + (size_t)(off + m0 + rowl) * H_DIM + col) = r;
                }
            }
        }
    }
}

// ---------------------------------------------------------------------------
// Combine
// ---------------------------------------------------------------------------
__global__ void combine(const float* __restrict__ wts, float* __restrict__ out) {
    int idx = blockIdx.x * blockDim.x + threadIdx.x;
    if (idx >= T_TOK * H_DIM / 4) return;
    int t  = idx / (H_DIM / 4);
    int h4 = idx % (H_DIM / 4);
    float w0 = wts[t * K_TOP + 0];
    float w1 = wts[t * K_TOP + 1];
    int s0 = g_slot[t * K_TOP + 0];
    int s1 = g_slot[t * K_TOP + 1];
    float4 a = ((const float4*)(g_eo + (size_t)s0 * H_DIM))[h4];
    float4 b = ((const float4*)(g_eo + (size_t)s1 * H_DIM))[h4];
    float4 r;
    r.x = w0 * a.x + w1 * b.x;
    r.y = w0 * a.y + w1 * b.y;
    r.z = w0 * a.z + w1 * b.z;
    r.w = w0 * a.w + w1 * b.w;
    ((float4*)out)[idx] = r;
}

// ---------------------------------------------------------------------------
// Launch
// ---------------------------------------------------------------------------
extern "C" void kernel_launch(void* const* d_in, const int* in_sizes, int n_in,
                              void* d_out, int out_size) {
    const float* X    = (const float*)d_in[0];
    const float* Wgu  = (const float*)d_in[1];
    const float* Wd   = (const float*)d_in[2];
    const int*   topk = (const int*)  d_in[3];
    const float* wts  = (const float*)d_in[4];
    float*       out  = (float*)d_out;

    cudaFuncSetAttribute(gemm1, cudaFuncAttributeMaxDynamicSharedMemorySize, SMEM_BYTES);
    cudaFuncSetAttribute(gemm2, cudaFuncAttributeMaxDynamicSharedMemorySize, SMEM_BYTES);

    route_all<<<1, 1024>>>(topk);
    conv_x  <<<512, 256>>>(X);
    conv_wgu<<<2048, 256>>>(Wgu);
    conv_wd <<<1024, 256>>>(Wd);

    dim3 g1(A_TOT / 128, I_DIM / 64, E_NUM);    // (32, 12, 8)
    gemm1<<<g1, 256, SMEM_BYTES>>>();

    dim3 g2(A_TOT / 128, H_DIM / 128, E_NUM);   // (32, 8, 8)
    gemm2<<<g2, 256, SMEM_BYTES>>>();

    combine<<<(T_TOK * H_DIM / 4 + 255) / 256, 256>>>(wts, out);
}

// round 7
// speedup vs baseline: 2.1406x; 1.4429x over previous
#include <cuda_runtime.h>
#include <cuda_fp16.h>
#include <stdint.h>

// Problem constants
#define T_TOK 2048
#define H_DIM 1024
#define I_DIM 768
#define E_NUM 8
#define K_TOP 2
#define A_TOT (T_TOK * K_TOP)   // 4096

// ---------------------------------------------------------------------------
// Device-global scratch
// ---------------------------------------------------------------------------
__device__ int   g_count[E_NUM];
__device__ int   g_offset[E_NUM];
__device__ int   g_perm[A_TOT];
__device__ int   g_slot[A_TOT];
__device__ __half g_x  [(size_t)T_TOK * H_DIM];
__device__ __half g_wgu[(size_t)E_NUM * 2 * I_DIM * H_DIM];
__device__ __half g_wd [(size_t)E_NUM * H_DIM * I_DIM];
__device__ __half g_act[(size_t)A_TOT * I_DIM];
__device__ float g_eo[(size_t)A_TOT * H_DIM];

// ---------------------------------------------------------------------------
// PTX helpers (base PTX, valid on sm_100 target)
// ---------------------------------------------------------------------------
__device__ __forceinline__ uint32_t smem_u32(const void* p) {
    uint32_t a;
    asm("{ .reg .u64 t; cvta.to.shared.u64 t, %1; cvt.u32.u64 %0, t; }" : "=r"(a) : "l"(p));
    return a;
}

#define LDSM_X4(R0, R1, R2, R3, ADDR) \
    asm volatile("ldmatrix.sync.aligned.m8n8.x4.shared.b16 {%0,%1,%2,%3}, [%4];" \
        : "=r"(R0), "=r"(R1), "=r"(R2), "=r"(R3) : "r"(ADDR))

#define MMA_F16(D, A, B0, B1) \
    asm volatile("mma.sync.aligned.m16n8k16.row.col.f32.f16.f16.f32 " \
        "{%0,%1,%2,%3}, {%4,%5,%6,%7}, {%8,%9}, {%0,%1,%2,%3};" \
        : "+f"((D)[0]), "+f"((D)[1]), "+f"((D)[2]), "+f"((D)[3]) \
        : "r"((A)[0]), "r"((A)[1]), "r"((A)[2]), "r"((A)[3]), "r"(B0), "r"(B1))

#define CP_ASYNC16(DST, SRC, SZ) \
    asm volatile("cp.async.cg.shared.global [%0], [%1], 16, %2;" \
        :: "r"(DST), "l"(SRC), "r"(SZ))
#define CP_COMMIT  asm volatile("cp.async.commit_group;" ::: "memory")
#define CP_WAIT1   asm volatile("cp.async.wait_group 1;" ::: "memory")
#define CP_WAIT0   asm volatile("cp.async.wait_group 0;" ::: "memory")

__device__ __forceinline__ uint32_t pack_h2(__half a, __half b) {
    return (uint32_t)__half_as_ushort(a) | ((uint32_t)__half_as_ushort(b) << 16);
}

// ---------------------------------------------------------------------------
// Fused conversion kernel: fp32 -> fp16 for X, Wgu, Wd
// ---------------------------------------------------------------------------
#define NX4  (T_TOK * H_DIM / 4)
#define NG4  (E_NUM * 2 * I_DIM * H_DIM / 4)
#define ND4  (E_NUM * H_DIM * I_DIM / 4)

__device__ __forceinline__ void conv_seg(const float* __restrict__ src,
                                         __half* __restrict__ dst, int n4,
                                         int start, int stride) {
    for (int i = start; i < n4; i += stride) {
        float4 v = ((const float4*)src)[i];
        uint2 u;
        u.x = pack_h2(__float2half_rn(v.x), __float2half_rn(v.y));
        u.y = pack_h2(__float2half_rn(v.z), __float2half_rn(v.w));
        ((uint2*)dst)[i] = u;
    }
}

__global__ void conv_all(const float* __restrict__ X,
                         const float* __restrict__ Wgu,
                         const float* __restrict__ Wd) {
    int start = blockIdx.x * blockDim.x + threadIdx.x;
    int stride = gridDim.x * blockDim.x;
    conv_seg(Wgu, g_wgu, NG4, start, stride);
    conv_seg(Wd,  g_wd,  ND4, start, stride);
    conv_seg(X,   g_x,   NX4, start, stride);
}

// ---------------------------------------------------------------------------
// Routing: single block
// ---------------------------------------------------------------------------
__global__ void route_all(const int* __restrict__ topk) {
    __shared__ int cnt[E_NUM], cur[E_NUM];
    int tid = threadIdx.x;
    if (tid < E_NUM) cnt[tid] = 0;
    __syncthreads();
    for (int a = tid; a < A_TOT; a += blockDim.x) atomicAdd(&cnt[topk[a]], 1);
    __syncthreads();
    if (tid == 0) {
        int s = 0;
        for (int e = 0; e < E_NUM; e++) {
            g_count[e] = cnt[e];
            g_offset[e] = s;
            cur[e] = s;
            s += cnt[e];
        }
    }
    __syncthreads();
    for (int a = tid; a < A_TOT; a += blockDim.x) {
        int e = topk[a];
        int s = atomicAdd(&cur[e], 1);
        g_perm[s] = a;
        g_slot[a] = s;
    }
}

// ---------------------------------------------------------------------------
// SMEM layout: KC=32 fp16 cols padded to stride 40.
// Per stage: A(128x40) | B(128x40)
// ---------------------------------------------------------------------------
#define KC       32
#define STRIDE   40
#define TILE_E   (128 * STRIDE)       // 5120 elems
#define STAGE_E  (2 * TILE_E)         // 10240
#define SMEM_BYTES (2 * STAGE_E * 2)  // 40960 B

__device__ __forceinline__ void load_afrag(uint32_t sb, int eoff, int row0, int kk,
                                           int lane, uint32_t a[4]) {
    int row = row0 + (lane & 15);
    int col = kk + ((lane >> 4) << 3);
    uint32_t addr = sb + (uint32_t)(eoff + row * STRIDE + col) * 2;
    LDSM_X4(a[0], a[1], a[2], a[3], addr);
}
__device__ __forceinline__ void load_bfrag(uint32_t sb, int eoff, int nbase, int kk,
                                           int lane, uint32_t b[4]) {
    int row = nbase + (((lane >> 4) & 1) << 3) + (lane & 7);
    int col = kk + (((lane >> 3) & 1) << 3);
    uint32_t addr = sb + (uint32_t)(eoff + row * STRIDE + col) * 2;
    LDSM_X4(b[0], b[1], b[2], b[3], addr);
}

// ---------------------------------------------------------------------------
// GEMM1: act = silu(X*Wg^T) * (X*Wu^T).  Block 128 slots x (64 gate + 64 up).
// 256 threads, 8 warps (4M x 2N), 2 CTAs/SM.  Single fp16 term.
// ---------------------------------------------------------------------------
#define NCH1 (H_DIM / KC)   // 32

__global__ __launch_bounds__(256, 2)
void gemm1(void) {
    const int e   = blockIdx.z;
    const int cnt = g_count[e];
    const int m0  = blockIdx.x * 128;
    if (m0 >= cnt) return;
    const int off  = g_offset[e];
    const int n0g  = blockIdx.y * 64;
    const int cntm = cnt - m0;

    extern __shared__ __half smem[];
    __shared__ int rowtok[128];
    const uint32_t sb = smem_u32(smem);

    const int tid = threadIdx.x, lane = tid & 31, wid = tid >> 5;
    const int wm = wid & 3, wn = wid >> 2;

    if (tid < 128)
        rowtok[tid] = (tid < cntm) ? g_perm[off + m0 + tid] / K_TOP : -1;
    __syncthreads();

    const __half* wb = g_wgu + (size_t)e * (2 * I_DIM) * H_DIM;

    // issue one stage: 1024 cp16, 4 per thread
    auto issue = [&](int k0, int soE) {
        #pragma unroll
        for (int i = 0; i < 4; i++) {
            int idx = tid + i * 256;
            int mat = idx >> 9;              // 0=A 1=B
            int row = (idx >> 2) & 127;
            int seg = idx & 3;
            uint32_t dst = sb + (uint32_t)(soE + mat * TILE_E + row * STRIDE + seg * 8) * 2;
            if (mat == 0) {
                int tok = rowtok[row];
                const __half* src = g_x + (size_t)(tok < 0 ? 0 : tok) * H_DIM + k0 + seg * 8;
                CP_ASYNC16(dst, src, (tok < 0) ? 0u : 16u);
            } else {
                int wr = (row < 64) ? (n0g + row) : (I_DIM + n0g + row - 64);
                const __half* src = wb + (size_t)wr * H_DIM + k0 + seg * 8;
                CP_ASYNC16(dst, src, 16u);
            }
        }
        CP_COMMIT;
    };

    float accG[2][4][4], accU[2][4][4];
    #pragma unroll
    for (int a = 0; a < 2; a++)
        #pragma unroll
        for (int b = 0; b < 4; b++)
            #pragma unroll
            for (int c = 0; c < 4; c++) { accG[a][b][c] = 0.f; accU[a][b][c] = 0.f; }

    issue(0, 0);

    for (int c = 0; c < NCH1; c++) {
        const int s = c & 1;
        if (c + 1 < NCH1) { issue((c + 1) * KC, (s ^ 1) * STAGE_E); CP_WAIT1; }
        else CP_WAIT0;
        __syncthreads();

        const int so = s * STAGE_E;
        #pragma unroll
        for (int kk = 0; kk < KC; kk += 16) {
            uint32_t ah[2][4];
            #pragma unroll
            for (int mt = 0; mt < 2; mt++)
                load_afrag(sb, so, wm * 32 + mt * 16, kk, lane, ah[mt]);
            #pragma unroll
            for (int p = 0; p < 2; p++) {
                const int nbg = wn * 32 + p * 16;
                uint32_t bg[4], bu[4];
                load_bfrag(sb, so + TILE_E, nbg,      kk, lane, bg);
                load_bfrag(sb, so + TILE_E, nbg + 64, kk, lane, bu);
                #pragma unroll
                for (int mt = 0; mt < 2; mt++) {
                    #pragma unroll
                    for (int q = 0; q < 2; q++) {
                        MMA_F16(accG[mt][2 * p + q], ah[mt], bg[2 * q], bg[2 * q + 1]);
                        MMA_F16(accU[mt][2 * p + q], ah[mt], bu[2 * q], bu[2 * q + 1]);
                    }
                }
            }
        }
        __syncthreads();
    }

    // epilogue: silu(gate)*up -> fp16 act
    const int gid = lane >> 2, tig = lane & 3;
    #pragma unroll
    for (int mt = 0; mt < 2; mt++) {
        #pragma unroll
        for (int nt = 0; nt < 4; nt++) {
            int colg = n0g + wn * 32 + nt * 8 + 2 * tig;
            #pragma unroll
            for (int h = 0; h < 2; h++) {
                int rowl = wm * 32 + mt * 16 + gid + h * 8;
                if (rowl < cntm) {
                    float g0 = accG[mt][nt][2 * h],     u0 = accU[mt][nt][2 * h];
                    float g1 = accG[mt][nt][2 * h + 1], u1 = accU[mt][nt][2 * h + 1];
                    float v0 = (g0 / (1.f + __expf(-g0))) * u0;
                    float v1 = (g1 / (1.f + __expf(-g1))) * u1;
                    size_t o = (size_t)(off + m0 + rowl) * I_DIM + colg;
                    *(uint32_t*)(g_act + o) = pack_h2(__float2half_rn(v0), __float2half_rn(v1));
                }
            }
        }
    }
}

// ---------------------------------------------------------------------------
// GEMM2: eo = act * Wd^T.  Block 128 slots x 128 H cols, K = 768.
// ---------------------------------------------------------------------------
#define NCH2 (I_DIM / KC)   // 24

__global__ __launch_bounds__(256, 2)
void gemm2(void) {
    const int e   = blockIdx.z;
    const int cnt = g_count[e];
    const int m0  = blockIdx.x * 128;
    if (m0 >= cnt) return;
    const int off  = g_offset[e];
    const int n0   = blockIdx.y * 128;
    const int cntm = cnt - m0;

    extern __shared__ __half smem[];
    const uint32_t sb = smem_u32(smem);

    const int tid = threadIdx.x, lane = tid & 31, wid = tid >> 5;
    const int wm = wid & 3, wn = wid >> 2;

    const __half* wb = g_wd + (size_t)e * H_DIM * I_DIM;

    auto issue = [&](int k0, int soE) {
        #pragma unroll
        for (int i = 0; i < 4; i++) {
            int idx = tid + i * 256;
            int mat = idx >> 9;
            int row = (idx >> 2) & 127;
            int seg = idx & 3;
            uint32_t dst = sb + (uint32_t)(soE + mat * TILE_E + row * STRIDE + seg * 8) * 2;
            if (mat == 0) {
                int r = (row < cntm) ? row : 0;
                const __half* src = g_act + (size_t)(off + m0 + r) * I_DIM + k0 + seg * 8;
                CP_ASYNC16(dst, src, (row < cntm) ? 16u : 0u);
            } else {
                const __half* src = wb + (size_t)(n0 + row) * I_DIM + k0 + seg * 8;
                CP_ASYNC16(dst, src, 16u);
            }
        }
        CP_COMMIT;
    };

    float acc[2][8][4];
    #pragma unroll
    for (int a = 0; a < 2; a++)
        #pragma unroll
        for (int b = 0; b < 8; b++)
            #pragma unroll
            for (int c = 0; c < 4; c++) acc[a][b][c] = 0.f;

    issue(0, 0);

    for (int c = 0; c < NCH2; c++) {
        const int s = c & 1;
        if (c + 1 < NCH2) { issue((c + 1) * KC, (s ^ 1) * STAGE_E); CP_WAIT1; }
        else CP_WAIT0;
        __syncthreads();

        const int so = s * STAGE_E;
        #pragma unroll
        for (int kk = 0; kk < KC; kk += 16) {
            uint32_t ah[2][4];
            #pragma unroll
            for (int mt = 0; mt < 2; mt++)
                load_afrag(sb, so, wm * 32 + mt * 16, kk, lane, ah[mt]);
            #pragma unroll
            for (int p = 0; p < 4; p++) {
                const int nb = wn * 64 + p * 16;
                uint32_t bh[4];
                load_bfrag(sb, so + TILE_E, nb, kk, lane, bh);
                #pragma unroll
                for (int mt = 0; mt < 2; mt++) {
                    #pragma unroll
                    for (int q = 0; q < 2; q++)
                        MMA_F16(acc[mt][2 * p + q], ah[mt], bh[2 * q], bh[2 * q + 1]);
                }
            }
        }
        __syncthreads();
    }

    const int gid = lane >> 2, tig = lane & 3;
    #pragma unroll
    for (int mt = 0; mt < 2; mt++) {
        #pragma unroll
        for (int nt = 0; nt < 8; nt++) {
            int col = n0 + wn * 64 + nt * 8 + 2 * tig;
            #pragma unroll
            for (int h = 0; h < 2; h++) {
                int rowl = wm * 32 + mt * 16 + gid + h * 8;
                if (rowl < cntm) {
                    float2 r = make_float2(acc[mt][nt][2 * h], acc[mt][nt][2 * h + 1]);
                    *(float2*)(g_eo + (size_t)(off + m0 + rowl) * H_DIM + col) = r;
                }
            }
        }
    }
}

// ---------------------------------------------------------------------------
// Combine
// ---------------------------------------------------------------------------
__global__ void combine(const float* __restrict__ wts, float* __restrict__ out) {
    int idx = blockIdx.x * blockDim.x + threadIdx.x;
    if (idx >= T_TOK * H_DIM / 4) return;
    int t  = idx / (H_DIM / 4);
    int h4 = idx % (H_DIM / 4);
    float w0 = wts[t * K_TOP + 0];
    float w1 = wts[t * K_TOP + 1];
    int s0 = g_slot[t * K_TOP + 0];
    int s1 = g_slot[t * K_TOP + 1];
    float4 a = ((const float4*)(g_eo + (size_t)s0 * H_DIM))[h4];
    float4 b = ((const float4*)(g_eo + (size_t)s1 * H_DIM))[h4];
    float4 r;
    r.x = w0 * a.x + w1 * b.x;
    r.y = w0 * a.y + w1 * b.y;
    r.z = w0 * a.z + w1 * b.z;
    r.w = w0 * a.w + w1 * b.w;
    ((float4*)out)[idx] = r;
}

// ---------------------------------------------------------------------------
// Launch
// ---------------------------------------------------------------------------
extern "C" void kernel_launch(void* const* d_in, const int* in_sizes, int n_in,
                              void* d_out, int out_size) {
    const float* X    = (const float*)d_in[0];
    const float* Wgu  = (const float*)d_in[1];
    const float* Wd   = (const float*)d_in[2];
    const int*   topk = (const int*)  d_in[3];
    const float* wts  = (const float*)d_in[4];
    float*       out  = (float*)d_out;

    cudaFuncSetAttribute(gemm1, cudaFuncAttributeMaxDynamicSharedMemorySize, SMEM_BYTES);
    cudaFuncSetAttribute(gemm2, cudaFuncAttributeMaxDynamicSharedMemorySize, SMEM_BYTES);

    route_all<<<1, 1024>>>(topk);
    conv_all<<<1184, 256>>>(X, Wgu, Wd);

    dim3 g1(A_TOT / 128, I_DIM / 64, E_NUM);    // (32, 12, 8)
    gemm1<<<g1, 256, SMEM_BYTES>>>();

    dim3 g2(A_TOT / 128, H_DIM / 128, E_NUM);   // (32, 8, 8)
    gemm2<<<g2, 256, SMEM_BYTES>>>();

    combine<<<(T_TOK * H_DIM / 4 + 255) / 256, 256>>>(wts, out);
}

// round 8
// speedup vs baseline: 2.5431x; 1.1880x over previous
#include <cuda_runtime.h>
#include <cuda_fp16.h>
#include <stdint.h>

// Problem constants
#define T_TOK 2048
#define H_DIM 1024
#define I_DIM 768
#define E_NUM 8
#define K_TOP 2
#define A_TOT (T_TOK * K_TOP)   // 4096

// ---------------------------------------------------------------------------
// Device-global scratch
// ---------------------------------------------------------------------------
__device__ int   g_count[E_NUM];
__device__ int   g_offset[E_NUM];
__device__ int   g_perm[A_TOT];
__device__ int   g_slot[A_TOT];
__device__ __half g_x  [(size_t)T_TOK * H_DIM];
__device__ __half g_wgu[(size_t)E_NUM * 2 * I_DIM * H_DIM];
__device__ __half g_wd [(size_t)E_NUM * H_DIM * I_DIM];
__device__ __half g_act[(size_t)A_TOT * I_DIM];
__device__ float g_eo[(size_t)A_TOT * H_DIM];

// ---------------------------------------------------------------------------
// PTX helpers (base PTX, valid on sm_100 target)
// ---------------------------------------------------------------------------
__device__ __forceinline__ uint32_t smem_u32(const void* p) {
    uint32_t a;
    asm("{ .reg .u64 t; cvta.to.shared.u64 t, %1; cvt.u32.u64 %0, t; }" : "=r"(a) : "l"(p));
    return a;
}

#define LDSM_X4(R0, R1, R2, R3, ADDR) \
    asm volatile("ldmatrix.sync.aligned.m8n8.x4.shared.b16 {%0,%1,%2,%3}, [%4];" \
        : "=r"(R0), "=r"(R1), "=r"(R2), "=r"(R3) : "r"(ADDR))

#define MMA_F16(D, A, B0, B1) \
    asm volatile("mma.sync.aligned.m16n8k16.row.col.f32.f16.f16.f32 " \
        "{%0,%1,%2,%3}, {%4,%5,%6,%7}, {%8,%9}, {%0,%1,%2,%3};" \
        : "+f"((D)[0]), "+f"((D)[1]), "+f"((D)[2]), "+f"((D)[3]) \
        : "r"((A)[0]), "r"((A)[1]), "r"((A)[2]), "r"((A)[3]), "r"(B0), "r"(B1))

#define CP_ASYNC16(DST, SRC, SZ) \
    asm volatile("cp.async.cg.shared.global [%0], [%1], 16, %2;" \
        :: "r"(DST), "l"(SRC), "r"(SZ))
#define CP_COMMIT  asm volatile("cp.async.commit_group;" ::: "memory")
#define CP_WAIT1   asm volatile("cp.async.wait_group 1;" ::: "memory")
#define CP_WAIT0   asm volatile("cp.async.wait_group 0;" ::: "memory")

__device__ __forceinline__ uint32_t pack_h2(__half a, __half b) {
    return (uint32_t)__half_as_ushort(a) | ((uint32_t)__half_as_ushort(b) << 16);
}

// ---------------------------------------------------------------------------
// Fused conversion kernel: fp32 -> fp16 for X, Wgu, Wd
// ---------------------------------------------------------------------------
#define NX4  (T_TOK * H_DIM / 4)
#define NG4  (E_NUM * 2 * I_DIM * H_DIM / 4)
#define ND4  (E_NUM * H_DIM * I_DIM / 4)

__device__ __forceinline__ void conv_seg(const float* __restrict__ src,
                                         __half* __restrict__ dst, int n4,
                                         int start, int stride) {
    for (int i = start; i < n4; i += stride) {
        float4 v = ((const float4*)src)[i];
        uint2 u;
        u.x = pack_h2(__float2half_rn(v.x), __float2half_rn(v.y));
        u.y = pack_h2(__float2half_rn(v.z), __float2half_rn(v.w));
        ((uint2*)dst)[i] = u;
    }
}

__global__ void conv_all(const float* __restrict__ X,
                         const float* __restrict__ Wgu,
                         const float* __restrict__ Wd) {
    int start = blockIdx.x * blockDim.x + threadIdx.x;
    int stride = gridDim.x * blockDim.x;
    conv_seg(Wgu, g_wgu, NG4, start, stride);
    conv_seg(Wd,  g_wd,  ND4, start, stride);
    conv_seg(X,   g_x,   NX4, start, stride);
}

// ---------------------------------------------------------------------------
// Routing: single block
// ---------------------------------------------------------------------------
__global__ void route_all(const int* __restrict__ topk) {
    __shared__ int cnt[E_NUM], cur[E_NUM];
    int tid = threadIdx.x;
    if (tid < E_NUM) cnt[tid] = 0;
    __syncthreads();
    for (int a = tid; a < A_TOT; a += blockDim.x) atomicAdd(&cnt[topk[a]], 1);
    __syncthreads();
    if (tid == 0) {
        int s = 0;
        for (int e = 0; e < E_NUM; e++) {
            g_count[e] = cnt[e];
            g_offset[e] = s;
            cur[e] = s;
            s += cnt[e];
        }
    }
    __syncthreads();
    for (int a = tid; a < A_TOT; a += blockDim.x) {
        int e = topk[a];
        int s = atomicAdd(&cur[e], 1);
        g_perm[s] = a;
        g_slot[a] = s;
    }
}

// ---------------------------------------------------------------------------
// SMEM layout: KC=64 fp16 cols padded to stride 72 (conflict-free ldmatrix:
// rows are 144B apart; within each 8-row ldsm phase addresses hit banks
// 0,16,32,...,112 mod 128).
// Per stage: A(128x72) | B(128x72).  2 stages = 72 KB/CTA, 2 CTAs/SM.
// ---------------------------------------------------------------------------
#define KC       64
#define STRIDE   72
#define TILE_E   (128 * STRIDE)       // 9216 elems
#define STAGE_E  (2 * TILE_E)         // 18432
#define SMEM_BYTES (2 * STAGE_E * 2)  // 73728 B

__device__ __forceinline__ void load_afrag(uint32_t sb, int eoff, int row0, int kk,
                                           int lane, uint32_t a[4]) {
    int row = row0 + (lane & 15);
    int col = kk + ((lane >> 4) << 3);
    uint32_t addr = sb + (uint32_t)(eoff + row * STRIDE + col) * 2;
    LDSM_X4(a[0], a[1], a[2], a[3], addr);
}
__device__ __forceinline__ void load_bfrag(uint32_t sb, int eoff, int nbase, int kk,
                                           int lane, uint32_t b[4]) {
    int row = nbase + (((lane >> 4) & 1) << 3) + (lane & 7);
    int col = kk + (((lane >> 3) & 1) << 3);
    uint32_t addr = sb + (uint32_t)(eoff + row * STRIDE + col) * 2;
    LDSM_X4(b[0], b[1], b[2], b[3], addr);
}

// ---------------------------------------------------------------------------
// GEMM1: act = silu(X*Wg^T) * (X*Wu^T).  Block 128 slots x (64 gate + 64 up).
// 256 threads, 8 warps (4M x 2N), 2 CTAs/SM.  Single fp16 term.
// ---------------------------------------------------------------------------
#define NCH1 (H_DIM / KC)   // 16

__global__ __launch_bounds__(256, 2)
void gemm1(void) {
    const int e   = blockIdx.z;
    const int cnt = g_count[e];
    const int m0  = blockIdx.x * 128;
    if (m0 >= cnt) return;
    const int off  = g_offset[e];
    const int n0g  = blockIdx.y * 64;
    const int cntm = cnt - m0;

    extern __shared__ __half smem[];
    __shared__ int rowtok[128];
    const uint32_t sb = smem_u32(smem);

    const int tid = threadIdx.x, lane = tid & 31, wid = tid >> 5;
    const int wm = wid & 3, wn = wid >> 2;

    if (tid < 128)
        rowtok[tid] = (tid < cntm) ? g_perm[off + m0 + tid] / K_TOP : -1;
    __syncthreads();

    const __half* wb = g_wgu + (size_t)e * (2 * I_DIM) * H_DIM;

    // issue one stage: 2048 cp16 (A 1024 + B 1024), 8 per thread
    auto issue = [&](int k0, int soE) {
        #pragma unroll
        for (int i = 0; i < 8; i++) {
            int idx = tid + i * 256;
            int mat = idx >> 10;             // 0=A 1=B
            int row = (idx >> 3) & 127;
            int seg = idx & 7;
            uint32_t dst = sb + (uint32_t)(soE + mat * TILE_E + row * STRIDE + seg * 8) * 2;
            if (mat == 0) {
                int tok = rowtok[row];
                const __half* src = g_x + (size_t)(tok < 0 ? 0 : tok) * H_DIM + k0 + seg * 8;
                CP_ASYNC16(dst, src, (tok < 0) ? 0u : 16u);
            } else {
                int wr = (row < 64) ? (n0g + row) : (I_DIM + n0g + row - 64);
                const __half* src = wb + (size_t)wr * H_DIM + k0 + seg * 8;
                CP_ASYNC16(dst, src, 16u);
            }
        }
        CP_COMMIT;
    };

    float accG[2][4][4], accU[2][4][4];
    #pragma unroll
    for (int a = 0; a < 2; a++)
        #pragma unroll
        for (int b = 0; b < 4; b++)
            #pragma unroll
            for (int c = 0; c < 4; c++) { accG[a][b][c] = 0.f; accU[a][b][c] = 0.f; }

    issue(0, 0);

    for (int c = 0; c < NCH1; c++) {
        const int s = c & 1;
        if (c + 1 < NCH1) { issue((c + 1) * KC, (s ^ 1) * STAGE_E); CP_WAIT1; }
        else CP_WAIT0;
        __syncthreads();

        const int so = s * STAGE_E;
        #pragma unroll
        for (int kk = 0; kk < KC; kk += 16) {
            // hoist ALL fragment loads for this kk, then all MMAs
            uint32_t ah[2][4], bg[2][4], bu[2][4];
            #pragma unroll
            for (int mt = 0; mt < 2; mt++)
                load_afrag(sb, so, wm * 32 + mt * 16, kk, lane, ah[mt]);
            #pragma unroll
            for (int p = 0; p < 2; p++) {
                load_bfrag(sb, so + TILE_E, wn * 32 + p * 16,      kk, lane, bg[p]);
                load_bfrag(sb, so + TILE_E, wn * 32 + p * 16 + 64, kk, lane, bu[p]);
            }
            #pragma unroll
            for (int p = 0; p < 2; p++) {
                #pragma unroll
                for (int mt = 0; mt < 2; mt++) {
                    #pragma unroll
                    for (int q = 0; q < 2; q++) {
                        MMA_F16(accG[mt][2 * p + q], ah[mt], bg[p][2 * q], bg[p][2 * q + 1]);
                        MMA_F16(accU[mt][2 * p + q], ah[mt], bu[p][2 * q], bu[p][2 * q + 1]);
                    }
                }
            }
        }
        __syncthreads();
    }

    // epilogue: silu(gate)*up -> fp16 act
    const int gid = lane >> 2, tig = lane & 3;
    #pragma unroll
    for (int mt = 0; mt < 2; mt++) {
        #pragma unroll
        for (int nt = 0; nt < 4; nt++) {
            int colg = n0g + wn * 32 + nt * 8 + 2 * tig;
            #pragma unroll
            for (int h = 0; h < 2; h++) {
                int rowl = wm * 32 + mt * 16 + gid + h * 8;
                if (rowl < cntm) {
                    float g0 = accG[mt][nt][2 * h],     u0 = accU[mt][nt][2 * h];
                    float g1 = accG[mt][nt][2 * h + 1], u1 = accU[mt][nt][2 * h + 1];
                    float v0 = (g0 / (1.f + __expf(-g0))) * u0;
                    float v1 = (g1 / (1.f + __expf(-g1))) * u1;
                    size_t o = (size_t)(off + m0 + rowl) * I_DIM + colg;
                    *(uint32_t*)(g_act + o) = pack_h2(__float2half_rn(v0), __float2half_rn(v1));
                }
            }
        }
    }
}

// ---------------------------------------------------------------------------
// GEMM2: eo = act * Wd^T.  Block 128 slots x 128 H cols, K = 768.
// ---------------------------------------------------------------------------
#define NCH2 (I_DIM / KC)   // 12

__global__ __launch_bounds__(256, 2)
void gemm2(void) {
    const int e   = blockIdx.z;
    const int cnt = g_count[e];
    const int m0  = blockIdx.x * 128;
    if (m0 >= cnt) return;
    const int off  = g_offset[e];
    const int n0   = blockIdx.y * 128;
    const int cntm = cnt - m0;

    extern __shared__ __half smem[];
    const uint32_t sb = smem_u32(smem);

    const int tid = threadIdx.x, lane = tid & 31, wid = tid >> 5;
    const int wm = wid & 3, wn = wid >> 2;

    const __half* wb = g_wd + (size_t)e * H_DIM * I_DIM;

    auto issue = [&](int k0, int soE) {
        #pragma unroll
        for (int i = 0; i < 8; i++) {
            int idx = tid + i * 256;
            int mat = idx >> 10;
            int row = (idx >> 3) & 127;
            int seg = idx & 7;
            uint32_t dst = sb + (uint32_t)(soE + mat * TILE_E + row * STRIDE + seg * 8) * 2;
            if (mat == 0) {
                int r = (row < cntm) ? row : 0;
                const __half* src = g_act + (size_t)(off + m0 + r) * I_DIM + k0 + seg * 8;
                CP_ASYNC16(dst, src, (row < cntm) ? 16u : 0u);
            } else {
                const __half* src = wb + (size_t)(n0 + row) * I_DIM + k0 + seg * 8;
                CP_ASYNC16(dst, src, 16u);
            }
        }
        CP_COMMIT;
    };

    float acc[2][8][4];
    #pragma unroll
    for (int a = 0; a < 2; a++)
        #pragma unroll
        for (int b = 0; b < 8; b++)
            #pragma unroll
            for (int c = 0; c < 4; c++) acc[a][b][c] = 0.f;

    issue(0, 0);

    for (int c = 0; c < NCH2; c++) {
        const int s = c & 1;
        if (c + 1 < NCH2) { issue((c + 1) * KC, (s ^ 1) * STAGE_E); CP_WAIT1; }
        else CP_WAIT0;
        __syncthreads();

        const int so = s * STAGE_E;
        #pragma unroll
        for (int kk = 0; kk < KC; kk += 16) {
            uint32_t ah[2][4], bh[4][4];
            #pragma unroll
            for (int mt = 0; mt < 2; mt++)
                load_afrag(sb, so, wm * 32 + mt * 16, kk, lane, ah[mt]);
            #pragma unroll
            for (int p = 0; p < 4; p++)
                load_bfrag(sb, so + TILE_E, wn * 64 + p * 16, kk, lane, bh[p]);
            #pragma unroll
            for (int p = 0; p < 4; p++) {
                #pragma unroll
                for (int mt = 0; mt < 2; mt++) {
                    #pragma unroll
                    for (int q = 0; q < 2; q++)
                        MMA_F16(acc[mt][2 * p + q], ah[mt], bh[p][2 * q], bh[p][2 * q + 1]);
                }
            }
        }
        __syncthreads();
    }

    const int gid = lane >> 2, tig = lane & 3;
    #pragma unroll
    for (int mt = 0; mt < 2; mt++) {
        #pragma unroll
        for (int nt = 0; nt < 8; nt++) {
            int col = n0 + wn * 64 + nt * 8 + 2 * tig;
            #pragma unroll
            for (int h = 0; h < 2; h++) {
                int rowl = wm * 32 + mt * 16 + gid + h * 8;
                if (rowl < cntm) {
                    float2 r = make_float2(acc[mt][nt][2 * h], acc[mt][nt][2 * h + 1]);
                    *(float2*)(g_eo + (size_t)(off + m0 + rowl) * H_DIM + col) = r;
                }
            }
        }
    }
}

// ---------------------------------------------------------------------------
// Combine
// ---------------------------------------------------------------------------
__global__ void combine(const float* __restrict__ wts, float* __restrict__ out) {
    int idx = blockIdx.x * blockDim.x + threadIdx.x;
    if (idx >= T_TOK * H_DIM / 4) return;
    int t  = idx / (H_DIM / 4);
    int h4 = idx % (H_DIM / 4);
    float w0 = wts[t * K_TOP + 0];
    float w1 = wts[t * K_TOP + 1];
    int s0 = g_slot[t * K_TOP + 0];
    int s1 = g_slot[t * K_TOP + 1];
    float4 a = ((const float4*)(g_eo + (size_t)s0 * H_DIM))[h4];
    float4 b = ((const float4*)(g_eo + (size_t)s1 * H_DIM))[h4];
    float4 r;
    r.x = w0 * a.x + w1 * b.x;
    r.y = w0 * a.y + w1 * b.y;
    r.z = w0 * a.z + w1 * b.z;
    r.w = w0 * a.w + w1 * b.w;
    ((float4*)out)[idx] = r;
}

// ---------------------------------------------------------------------------
// Launch
// ---------------------------------------------------------------------------
extern "C" void kernel_launch(void* const* d_in, const int* in_sizes, int n_in,
                              void* d_out, int out_size) {
    const float* X    = (const float*)d_in[0];
    const float* Wgu  = (const float*)d_in[1];
    const float* Wd   = (const float*)d_in[2];
    const int*   topk = (const int*)  d_in[3];
    const float* wts  = (const float*)d_in[4];
    float*       out  = (float*)d_out;

    cudaFuncSetAttribute(gemm1, cudaFuncAttributeMaxDynamicSharedMemorySize, SMEM_BYTES);
    cudaFuncSetAttribute(gemm2, cudaFuncAttributeMaxDynamicSharedMemorySize, SMEM_BYTES);

    route_all<<<1, 1024>>>(topk);
    conv_all<<<1184, 256>>>(X, Wgu, Wd);

    dim3 g1(A_TOT / 128, I_DIM / 64, E_NUM);    // (32, 12, 8)
    gemm1<<<g1, 256, SMEM_BYTES>>>();

    dim3 g2(A_TOT / 128, H_DIM / 128, E_NUM);   // (32, 8, 8)
    gemm2<<<g2, 256, SMEM_BYTES>>>();

    combine<<<(T_TOK * H_DIM / 4 + 255) / 256, 256>>>(wts, out);
}